// round 3
// baseline (speedup 1.0000x reference)
#include <cuda_runtime.h>
#include <cuda_bf16.h>

#define FULL 0xffffffffu
#define NROWS 65536          // B*N
#define FD 256               // feature dim
#define MMEM 4096            // memory size
#define NCAND 16             // candidates kept (top-16), exact rescore picks top-8
#define TOPK 8

// -------- scratch (static __device__ — no allocations) --------
__device__ float         g_q[(size_t)NROWS * FD];     // exact fp32 q = query@Wq + bq
__device__ __nv_bfloat16 g_qb[(size_t)NROWS * FD];    // bf16 copy of q
__device__ __nv_bfloat16 g_kb[(size_t)MMEM * FD];     // bf16 memory_keys
__device__ int           g_cand[(size_t)NROWS * NCAND];
__device__ float         g_ret[(size_t)NROWS * FD];   // retrieved
__device__ float         g_h[(size_t)NROWS * FD];     // relu hidden

// ============================================================
// keys -> bf16
// ============================================================
__global__ void conv_keys_kernel(const float* __restrict__ keys,
                                 __nv_bfloat16* __restrict__ out) {
    int i = blockIdx.x * blockDim.x + threadIdx.x;   // over MMEM*FD/4
    float4 v = ((const float4*)keys)[i];
    union { __nv_bfloat16 h[4]; uint2 u; } p;
    p.h[0] = __float2bfloat16_rn(v.x);
    p.h[1] = __float2bfloat16_rn(v.y);
    p.h[2] = __float2bfloat16_rn(v.z);
    p.h[3] = __float2bfloat16_rn(v.w);
    ((uint2*)out)[i] = p.u;
}

// ============================================================
// generic fp32 SGEMM: C[M,N] = A[M,K] @ B[K,N] + bias, optional relu,
// optional bf16 secondary output. BM=BN=128, BK=8, 256 thr, 8x8 microtile.
// All dims multiples of tile sizes here (M=65536, N=256, K=256/512).
// ============================================================
template <int RELU, int WBF>
__global__ __launch_bounds__(256)
void sgemm128(const float* __restrict__ A, const float* __restrict__ B,
              const float* __restrict__ bias, float* __restrict__ C,
              __nv_bfloat16* __restrict__ Cb, int N, int K) {
    __shared__ float As[8][128];
    __shared__ float Bs[8][128];
    int tid = threadIdx.x;
    int row0 = blockIdx.x * 128;
    int col0 = blockIdx.y * 128;
    int tx = tid & 15, ty = tid >> 4;
    int arow = tid >> 1, akq = (tid & 1) * 4;
    int brow = tid >> 5, bcol = (tid & 31) * 4;

    float acc[8][8];
#pragma unroll
    for (int i = 0; i < 8; i++)
#pragma unroll
        for (int j = 0; j < 8; j++) acc[i][j] = 0.f;

    for (int kb = 0; kb < K; kb += 8) {
        float4 va = *(const float4*)(A + (size_t)(row0 + arow) * K + kb + akq);
        As[akq + 0][arow] = va.x; As[akq + 1][arow] = va.y;
        As[akq + 2][arow] = va.z; As[akq + 3][arow] = va.w;
        float4 vb = *(const float4*)(B + (size_t)(kb + brow) * N + col0 + bcol);
        *(float4*)&Bs[brow][bcol] = vb;
        __syncthreads();
#pragma unroll
        for (int kk = 0; kk < 8; kk++) {
            float a[8], b[8];
            *(float4*)(a)     = *(float4*)&As[kk][ty * 8];
            *(float4*)(a + 4) = *(float4*)&As[kk][ty * 8 + 4];
            *(float4*)(b)     = *(float4*)&Bs[kk][tx * 8];
            *(float4*)(b + 4) = *(float4*)&Bs[kk][tx * 8 + 4];
#pragma unroll
            for (int i = 0; i < 8; i++)
#pragma unroll
                for (int j = 0; j < 8; j++) acc[i][j] = fmaf(a[i], b[j], acc[i][j]);
        }
        __syncthreads();
    }
#pragma unroll
    for (int i = 0; i < 8; i++) {
        int r = row0 + ty * 8 + i;
#pragma unroll
        for (int j = 0; j < 8; j++) {
            int c = col0 + tx * 8 + j;
            float v = acc[i][j] + bias[c];
            if (RELU) v = fmaxf(v, 0.f);
            C[(size_t)r * N + c] = v;
            if (WBF) Cb[(size_t)r * N + c] = __float2bfloat16_rn(v);
        }
    }
}

// ============================================================
// SGEMM over concat([query, retrieved]) @ W1 + b1, relu -> h   (K=512)
// ============================================================
__global__ __launch_bounds__(256)
void sgemm_concat(const float* __restrict__ Aq, const float* __restrict__ Ar,
                  const float* __restrict__ B, const float* __restrict__ bias,
                  float* __restrict__ C) {
    const int N = 256, K = 512;
    __shared__ float As[8][128];
    __shared__ float Bs[8][128];
    int tid = threadIdx.x;
    int row0 = blockIdx.x * 128;
    int col0 = blockIdx.y * 128;
    int tx = tid & 15, ty = tid >> 4;
    int arow = tid >> 1, akq = (tid & 1) * 4;
    int brow = tid >> 5, bcol = (tid & 31) * 4;

    float acc[8][8];
#pragma unroll
    for (int i = 0; i < 8; i++)
#pragma unroll
        for (int j = 0; j < 8; j++) acc[i][j] = 0.f;

    for (int kb = 0; kb < K; kb += 8) {
        int kg = kb + akq;  // multiple of 4; never straddles the 256 boundary
        const float* src = (kg < 256)
            ? (Aq + (size_t)(row0 + arow) * 256 + kg)
            : (Ar + (size_t)(row0 + arow) * 256 + (kg - 256));
        float4 va = *(const float4*)src;
        As[akq + 0][arow] = va.x; As[akq + 1][arow] = va.y;
        As[akq + 2][arow] = va.z; As[akq + 3][arow] = va.w;
        float4 vb = *(const float4*)(B + (size_t)(kb + brow) * N + col0 + bcol);
        *(float4*)&Bs[brow][bcol] = vb;
        __syncthreads();
#pragma unroll
        for (int kk = 0; kk < 8; kk++) {
            float a[8], b[8];
            *(float4*)(a)     = *(float4*)&As[kk][ty * 8];
            *(float4*)(a + 4) = *(float4*)&As[kk][ty * 8 + 4];
            *(float4*)(b)     = *(float4*)&Bs[kk][tx * 8];
            *(float4*)(b + 4) = *(float4*)&Bs[kk][tx * 8 + 4];
#pragma unroll
            for (int i = 0; i < 8; i++)
#pragma unroll
                for (int j = 0; j < 8; j++) acc[i][j] = fmaf(a[i], b[j], acc[i][j]);
        }
        __syncthreads();
    }
#pragma unroll
    for (int i = 0; i < 8; i++) {
        int r = row0 + ty * 8 + i;
#pragma unroll
        for (int j = 0; j < 8; j++) {
            int c = col0 + tx * 8 + j;
            float v = fmaxf(acc[i][j] + bias[c], 0.f);
            C[(size_t)r * N + c] = v;
        }
    }
}

// ============================================================
// Fused sim GEMM (bf16 mma.sync) + streaming top-16 candidates.
// 128-query tile per CTA, 32 chunks of 128 keys, K=256.
// 8 warps as 4(m) x 2(n); warp tile 32x64; mma m16n8k16.
// ============================================================
#define QPAD 264   // 256 + 8 bf16 pad (conflict-free fragment LDS)
#define SPAD 132   // sim row stride in floats
#define SIM_SMEM (128*QPAD*2 /*q*/ + 128*QPAD*2 /*keys*/ + 128*SPAD*4 /*sim*/ \
                  + 128*NCAND*4 /*tv*/ + 128*NCAND*4 /*ti*/)

__global__ __launch_bounds__(256, 1)
void sim_topk_kernel(const __nv_bfloat16* __restrict__ qb,
                     const __nv_bfloat16* __restrict__ kb,
                     int* __restrict__ cand) {
    extern __shared__ char smraw[];
    __nv_bfloat16* qs = (__nv_bfloat16*)smraw;            // [128][QPAD]
    __nv_bfloat16* ks = qs + 128 * QPAD;                  // [128][QPAD]
    float* sim = (float*)(ks + 128 * QPAD);               // [128][SPAD]
    float* tv  = sim + 128 * SPAD;                        // [128][16]
    int*   ti  = (int*)(tv + 128 * NCAND);                // [128][16]

    int tid = threadIdx.x, lane = tid & 31, warp = tid >> 5;
    int row0 = blockIdx.x * 128;

    // load q tile (bf16, already converted)
    for (int i = tid; i < 128 * 32; i += 256) {
        int r = i >> 5, u = i & 31;
        uint4 v = *(const uint4*)(qb + (size_t)(row0 + r) * 256 + u * 8);
        *(uint4*)(qs + r * QPAD + u * 8) = v;
    }
    for (int i = tid; i < 128 * NCAND; i += 256) { tv[i] = -1e30f; ti[i] = 0; }
    __syncthreads();

    int wm = warp >> 1, wn = warp & 1;
    int qr = lane >> 2, kc = (lane & 3) * 2;

    for (int ch = 0; ch < 32; ch++) {
        // stream keys chunk into smem
        for (int i = tid; i < 128 * 32; i += 256) {
            int r = i >> 5, u = i & 31;
            uint4 v = *(const uint4*)(kb + (size_t)(ch * 128 + r) * 256 + u * 8);
            *(uint4*)(ks + r * QPAD + u * 8) = v;
        }
        __syncthreads();

        float acc[2][8][4];
#pragma unroll
        for (int mt = 0; mt < 2; mt++)
#pragma unroll
            for (int nt = 0; nt < 8; nt++)
#pragma unroll
                for (int x = 0; x < 4; x++) acc[mt][nt][x] = 0.f;

#pragma unroll
        for (int ksp = 0; ksp < 16; ksp++) {
            int k0 = ksp * 16;
            unsigned A[2][4];
#pragma unroll
            for (int mt = 0; mt < 2; mt++) {
                const __nv_bfloat16* p0 = qs + (wm * 32 + mt * 16 + qr) * QPAD + k0 + kc;
                A[mt][0] = *(const unsigned*)(p0);
                A[mt][1] = *(const unsigned*)(p0 + 8 * QPAD);
                A[mt][2] = *(const unsigned*)(p0 + 8);
                A[mt][3] = *(const unsigned*)(p0 + 8 * QPAD + 8);
            }
#pragma unroll
            for (int nt = 0; nt < 8; nt++) {
                const __nv_bfloat16* pb = ks + (wn * 64 + nt * 8 + qr) * QPAD + k0 + kc;
                unsigned B0 = *(const unsigned*)(pb);
                unsigned B1 = *(const unsigned*)(pb + 8);
#pragma unroll
                for (int mt = 0; mt < 2; mt++) {
                    asm volatile(
                        "mma.sync.aligned.m16n8k16.row.col.f32.bf16.bf16.f32 "
                        "{%0,%1,%2,%3}, {%4,%5,%6,%7}, {%8,%9}, {%0,%1,%2,%3};\n"
                        : "+f"(acc[mt][nt][0]), "+f"(acc[mt][nt][1]),
                          "+f"(acc[mt][nt][2]), "+f"(acc[mt][nt][3])
                        : "r"(A[mt][0]), "r"(A[mt][1]), "r"(A[mt][2]), "r"(A[mt][3]),
                          "r"(B0), "r"(B1));
                }
            }
        }

        // stage sim tile to smem
#pragma unroll
        for (int mt = 0; mt < 2; mt++)
#pragma unroll
            for (int nt = 0; nt < 8; nt++) {
                int r = wm * 32 + mt * 16 + qr;
                int c = wn * 64 + nt * 8 + (lane & 3) * 2;
                *(float2*)&sim[r * SPAD + c] = make_float2(acc[mt][nt][0], acc[mt][nt][1]);
                *(float2*)&sim[(r + 8) * SPAD + c] = make_float2(acc[mt][nt][2], acc[mt][nt][3]);
            }
        __syncthreads();

        // streaming top-16 maintenance: warp owns rows warp*16..+15
        for (int rr = 0; rr < 16; rr++) {
            int r = warp * 16 + rr;
            float* tvr = tv + r * NCAND;
            int*   tir = ti + r * NCAND;
            float thresh = tvr[NCAND - 1];
#pragma unroll
            for (int j = 0; j < 4; j++) {
                float v = sim[r * SPAD + lane + j * 32];
                unsigned bal = __ballot_sync(FULL, v > thresh);
                while (bal) {
                    int src = __ffs(bal) - 1; bal &= bal - 1;
                    float vv = __shfl_sync(FULL, v, src);
                    if (vv > thresh) {
                        if (lane == 0) {
                            int p = NCAND - 1;
                            while (p > 0 && tvr[p - 1] < vv) {
                                tvr[p] = tvr[p - 1]; tir[p] = tir[p - 1]; p--;
                            }
                            tvr[p] = vv; tir[p] = ch * 128 + src + j * 32;
                        }
                        __syncwarp();
                        thresh = tvr[NCAND - 1];
                    }
                }
            }
        }
        __syncthreads();
    }

    for (int rr = 0; rr < 16; rr++) {
        int r = warp * 16 + rr;
        if (lane < NCAND) cand[(size_t)(row0 + r) * NCAND + lane] = ti[r * NCAND + lane];
    }
}

// ============================================================
// Exact rescore: fp32 dots for 16 candidates, exact top-8,
// softmax + weighted gather of memory_values. 1 warp per query.
// ============================================================
__global__ __launch_bounds__(256)
void rescore_kernel(const float* __restrict__ q, const float* __restrict__ keys,
                    const float* __restrict__ values, const int* __restrict__ cand,
                    float* __restrict__ ret) {
    int lane = threadIdx.x & 31, warp = threadIdx.x >> 5;
    int g = blockIdx.x * 8 + warp;

    float qv[8];
#pragma unroll
    for (int k = 0; k < 8; k++) qv[k] = q[(size_t)g * 256 + k * 32 + lane];

    int myc = cand[(size_t)g * NCAND + (lane & 15)];
    float s[NCAND]; int kid[NCAND];
#pragma unroll
    for (int c = 0; c < NCAND; c++) {
        int ki = __shfl_sync(FULL, myc, c);
        kid[c] = ki;
        const float* kr = keys + (size_t)ki * 256;
        float d = 0.f;
#pragma unroll
        for (int k = 0; k < 8; k++) d = fmaf(qv[k], kr[k * 32 + lane], d);
#pragma unroll
        for (int o = 16; o; o >>= 1) d += __shfl_xor_sync(FULL, d, o);
        s[c] = d;   // identical across lanes
    }

    bool sel[NCAND];
    float mx = -1e30f;
#pragma unroll
    for (int c = 0; c < NCAND; c++) {
        int rk = 0;
#pragma unroll
        for (int j = 0; j < NCAND; j++)
            rk += (s[j] > s[c]) || (s[j] == s[c] && j < c);
        sel[c] = (rk < TOPK);
        if (sel[c]) mx = fmaxf(mx, s[c]);
    }
    float den = 0.f, w[NCAND];
#pragma unroll
    for (int c = 0; c < NCAND; c++) {
        w[c] = sel[c] ? __expf(s[c] - mx) : 0.f;
        den += w[c];
    }
    float inv = 1.f / den;

    float accf[8];
#pragma unroll
    for (int k = 0; k < 8; k++) accf[k] = 0.f;
#pragma unroll
    for (int c = 0; c < NCAND; c++) {
        if (sel[c]) {
            const float* vr = values + (size_t)kid[c] * 256;
            float wc = w[c] * inv;
#pragma unroll
            for (int k = 0; k < 8; k++) accf[k] = fmaf(wc, vr[k * 32 + lane], accf[k]);
        }
    }
#pragma unroll
    for (int k = 0; k < 8; k++) ret[(size_t)g * 256 + k * 32 + lane] = accf[k];
}

// ============================================================
// launch
// ============================================================
extern "C" void kernel_launch(void* const* d_in, const int* in_sizes, int n_in,
                              void* d_out, int out_size) {
    const float* query = (const float*)d_in[0];
    const float* mkeys = (const float*)d_in[1];
    const float* mvals = (const float*)d_in[2];
    const float* Wq    = (const float*)d_in[3];
    const float* bq    = (const float*)d_in[4];
    const float* W1    = (const float*)d_in[5];
    const float* b1    = (const float*)d_in[6];
    const float* W2    = (const float*)d_in[7];
    const float* b2    = (const float*)d_in[8];
    float* out = (float*)d_out;
    (void)in_sizes; (void)n_in; (void)out_size;

    float* qf;           cudaGetSymbolAddress((void**)&qf, g_q);
    __nv_bfloat16* qbf;  cudaGetSymbolAddress((void**)&qbf, g_qb);
    __nv_bfloat16* kbf;  cudaGetSymbolAddress((void**)&kbf, g_kb);
    int* candp;          cudaGetSymbolAddress((void**)&candp, g_cand);
    float* retp;         cudaGetSymbolAddress((void**)&retp, g_ret);
    float* hp;           cudaGetSymbolAddress((void**)&hp, g_h);

    // keys -> bf16
    conv_keys_kernel<<<(MMEM * FD / 4) / 256, 256>>>(mkeys, kbf);

    // q = query @ Wq + bq  (fp32 exact + bf16 copy)
    sgemm128<0, 1><<<dim3(NROWS / 128, 2), 256>>>(query, Wq, bq, qf, qbf, 256, 256);

    // fused sim + top-16 candidates (bf16 tensor cores)
    cudaFuncSetAttribute(sim_topk_kernel,
                         cudaFuncAttributeMaxDynamicSharedMemorySize, SIM_SMEM);
    sim_topk_kernel<<<NROWS / 128, 256, SIM_SMEM>>>(qbf, kbf, candp);

    // exact rescore + softmax + gather
    rescore_kernel<<<NROWS / 8, 256>>>(qf, mkeys, mvals, candp, retp);

    // MLP
    sgemm_concat<<<dim3(NROWS / 128, 2), 256>>>(query, retp, W1, b1, hp);
    sgemm128<0, 0><<<dim3(NROWS / 128, 2), 256>>>(hp, W2, b2, out, nullptr, 256, 256);
}

// round 4
// speedup vs baseline: 1.1664x; 1.1664x over previous
#include <cuda_runtime.h>
#include <cuda_bf16.h>

#define FULL 0xffffffffu
#define NROWS 65536          // B*N
#define FD 256               // feature dim
#define MMEM 4096            // memory size
#define NCAND 16             // candidates kept (top-16), exact rescore picks top-8
#define TOPK 8

// -------- scratch (static __device__ — no allocations) --------
__device__ float         g_q[(size_t)NROWS * FD];     // exact fp32 q = query@Wq + bq
__device__ __nv_bfloat16 g_qb[(size_t)NROWS * FD];    // bf16 copy of q
__device__ __nv_bfloat16 g_kb[(size_t)MMEM * FD];     // bf16 memory_keys
__device__ int           g_cand[(size_t)NROWS * NCAND];
__device__ float         g_ret[(size_t)NROWS * FD];   // retrieved
__device__ float         g_h[(size_t)NROWS * FD];     // relu hidden

// split-bf16 transposed weights: [N=256][K] k-major, hi + lo
__device__ __nv_bfloat16 g_wqt_h[256 * 256], g_wqt_l[256 * 256];
__device__ __nv_bfloat16 g_w1t_h[256 * 512], g_w1t_l[256 * 512];
__device__ __nv_bfloat16 g_w2t_h[256 * 256], g_w2t_l[256 * 256];

// ============================================================
// keys -> bf16
// ============================================================
__global__ void conv_keys_kernel(const float* __restrict__ keys,
                                 __nv_bfloat16* __restrict__ out) {
    int i = blockIdx.x * blockDim.x + threadIdx.x;   // over MMEM*FD/4
    float4 v = ((const float4*)keys)[i];
    union { __nv_bfloat16 h[4]; uint2 u; } p;
    p.h[0] = __float2bfloat16_rn(v.x);
    p.h[1] = __float2bfloat16_rn(v.y);
    p.h[2] = __float2bfloat16_rn(v.z);
    p.h[3] = __float2bfloat16_rn(v.w);
    ((uint2*)out)[i] = p.u;
}

// ============================================================
// weight prep: W[K][256] -> transposed split-bf16 [256 n][K k]
// ============================================================
__global__ void prep_wt_kernel(const float* __restrict__ W, int K,
                               __nv_bfloat16* __restrict__ th,
                               __nv_bfloat16* __restrict__ tl) {
    int idx = blockIdx.x * 256 + threadIdx.x;   // over 256*K
    int n = idx / K, k = idx - n * K;
    float v = W[(size_t)k * 256 + n];
    __nv_bfloat16 h = __float2bfloat16_rn(v);
    float r = v - __bfloat162float(h);
    th[(size_t)n * K + k] = h;
    tl[(size_t)n * K + k] = __float2bfloat16_rn(r);
}

// ============================================================
// split-bf16 tensor-core GEMM:
//   C[M,256] = A[M,K] @ W[K,256] + bias   (fp32-class accuracy via hi/lo)
// BM=128, BN=128, BK=64. 256 thr, 8 warps (4m x 2n), warp tile 32x64.
// CONCAT: A = [Aq | Ar] along K (each row-stride 256, K=512).
// ============================================================
#define APAD 72   // row stride (bf16) for staged tiles: 64 + 8 pad
#define BG_SMEM (4 * 128 * APAD * 2)   // As_hi, As_lo, Bs_hi, Bs_lo

template <int K, int CONCAT, int RELU, int WBF>
__global__ __launch_bounds__(256)
void bgemm_kernel(const float* __restrict__ Aq, const float* __restrict__ Ar,
                  const __nv_bfloat16* __restrict__ Bth,
                  const __nv_bfloat16* __restrict__ Btl,
                  const float* __restrict__ bias,
                  float* __restrict__ C, __nv_bfloat16* __restrict__ Cb) {
    extern __shared__ char smraw[];
    __nv_bfloat16* Ash = (__nv_bfloat16*)smraw;     // [128][APAD]
    __nv_bfloat16* Asl = Ash + 128 * APAD;
    __nv_bfloat16* Bsh = Asl + 128 * APAD;
    __nv_bfloat16* Bsl = Bsh + 128 * APAD;

    int tid = threadIdx.x, lane = tid & 31, warp = tid >> 5;
    int row0 = blockIdx.x * 128;
    int col0 = blockIdx.y * 128;
    int wm = warp >> 1, wn = warp & 1;
    int qr = lane >> 2, kc = (lane & 3) * 2;

    float acc[2][8][4];
#pragma unroll
    for (int mt = 0; mt < 2; mt++)
#pragma unroll
        for (int nt = 0; nt < 8; nt++)
#pragma unroll
            for (int x = 0; x < 4; x++) acc[mt][nt][x] = 0.f;

    for (int kb = 0; kb < K; kb += 64) {
        // ---- stage A chunk (fp32 -> hi/lo bf16) ----
        const float* Asrc; int astr;
        if (CONCAT) {
            if (kb < 256) { Asrc = Aq + kb;         astr = 256; }
            else          { Asrc = Ar + (kb - 256); astr = 256; }
        } else { Asrc = Aq + kb; astr = K; }
#pragma unroll
        for (int t = 0; t < 8; t++) {
            int gidx = tid + t * 256;               // over 2048 float4
            int r = gidx >> 4, kq = (gidx & 15) * 4;
            float4 v = *(const float4*)(Asrc + (size_t)(row0 + r) * astr + kq);
            union { __nv_bfloat16 h[4]; uint2 u; } ph, pl;
            float f[4] = {v.x, v.y, v.z, v.w};
#pragma unroll
            for (int j = 0; j < 4; j++) {
                ph.h[j] = __float2bfloat16_rn(f[j]);
                pl.h[j] = __float2bfloat16_rn(f[j] - __bfloat162float(ph.h[j]));
            }
            *(uint2*)(Ash + r * APAD + kq) = ph.u;
            *(uint2*)(Asl + r * APAD + kq) = pl.u;
        }
        // ---- stage B chunk (preconverted, [n][k] bf16) ----
#pragma unroll
        for (int t = 0; t < 4; t++) {
            int gidx = tid + t * 256;               // over 1024 uint4
            int n = gidx >> 3, q = (gidx & 7) * 8;
            uint4 vh = *(const uint4*)(Bth + (size_t)(col0 + n) * K + kb + q);
            uint4 vl = *(const uint4*)(Btl + (size_t)(col0 + n) * K + kb + q);
            *(uint4*)(Bsh + n * APAD + q) = vh;
            *(uint4*)(Bsl + n * APAD + q) = vl;
        }
        __syncthreads();

#pragma unroll
        for (int ksp = 0; ksp < 4; ksp++) {
            int k0 = ksp * 16;
            unsigned Ah[2][4], Al[2][4];
#pragma unroll
            for (int mt = 0; mt < 2; mt++) {
                const __nv_bfloat16* ph = Ash + (wm * 32 + mt * 16 + qr) * APAD + k0 + kc;
                const __nv_bfloat16* pl = Asl + (wm * 32 + mt * 16 + qr) * APAD + k0 + kc;
                Ah[mt][0] = *(const unsigned*)(ph);
                Ah[mt][1] = *(const unsigned*)(ph + 8 * APAD);
                Ah[mt][2] = *(const unsigned*)(ph + 8);
                Ah[mt][3] = *(const unsigned*)(ph + 8 * APAD + 8);
                Al[mt][0] = *(const unsigned*)(pl);
                Al[mt][1] = *(const unsigned*)(pl + 8 * APAD);
                Al[mt][2] = *(const unsigned*)(pl + 8);
                Al[mt][3] = *(const unsigned*)(pl + 8 * APAD + 8);
            }
#pragma unroll
            for (int nt = 0; nt < 8; nt++) {
                const __nv_bfloat16* pbh = Bsh + (wn * 64 + nt * 8 + qr) * APAD + k0 + kc;
                const __nv_bfloat16* pbl = Bsl + (wn * 64 + nt * 8 + qr) * APAD + k0 + kc;
                unsigned Bh0 = *(const unsigned*)(pbh);
                unsigned Bh1 = *(const unsigned*)(pbh + 8);
                unsigned Bl0 = *(const unsigned*)(pbl);
                unsigned Bl1 = *(const unsigned*)(pbl + 8);
#pragma unroll
                for (int mt = 0; mt < 2; mt++) {
#define MMA_BF16(Areg, B0, B1)                                              \
    asm volatile(                                                           \
        "mma.sync.aligned.m16n8k16.row.col.f32.bf16.bf16.f32 "              \
        "{%0,%1,%2,%3}, {%4,%5,%6,%7}, {%8,%9}, {%0,%1,%2,%3};\n"           \
        : "+f"(acc[mt][nt][0]), "+f"(acc[mt][nt][1]),                       \
          "+f"(acc[mt][nt][2]), "+f"(acc[mt][nt][3])                        \
        : "r"(Areg[mt][0]), "r"(Areg[mt][1]), "r"(Areg[mt][2]),             \
          "r"(Areg[mt][3]), "r"(B0), "r"(B1))
                    MMA_BF16(Ah, Bh0, Bh1);   // hi*hi
                    MMA_BF16(Ah, Bl0, Bl1);   // hi*lo
                    MMA_BF16(Al, Bh0, Bh1);   // lo*hi
#undef MMA_BF16
                }
            }
        }
        __syncthreads();
    }

    // epilogue
#pragma unroll
    for (int mt = 0; mt < 2; mt++) {
        int rA = row0 + wm * 32 + mt * 16 + qr;
#pragma unroll
        for (int nt = 0; nt < 8; nt++) {
            int c = col0 + wn * 64 + nt * 8 + (lane & 3) * 2;
            float b0 = bias[c], b1 = bias[c + 1];
            float v0 = acc[mt][nt][0] + b0, v1 = acc[mt][nt][1] + b1;
            float v2 = acc[mt][nt][2] + b0, v3 = acc[mt][nt][3] + b1;
            if (RELU) {
                v0 = fmaxf(v0, 0.f); v1 = fmaxf(v1, 0.f);
                v2 = fmaxf(v2, 0.f); v3 = fmaxf(v3, 0.f);
            }
            *(float2*)(C + (size_t)rA * 256 + c)       = make_float2(v0, v1);
            *(float2*)(C + (size_t)(rA + 8) * 256 + c) = make_float2(v2, v3);
            if (WBF) {
                union { __nv_bfloat16 h[2]; unsigned u; } p;
                p.h[0] = __float2bfloat16_rn(v0); p.h[1] = __float2bfloat16_rn(v1);
                *(unsigned*)(Cb + (size_t)rA * 256 + c) = p.u;
                p.h[0] = __float2bfloat16_rn(v2); p.h[1] = __float2bfloat16_rn(v3);
                *(unsigned*)(Cb + (size_t)(rA + 8) * 256 + c) = p.u;
            }
        }
    }
}

// ============================================================
// Fused sim GEMM (bf16 mma.sync) + streaming top-16 candidates.
// 128-query tile per CTA, 32 chunks of 128 keys, K=256.
// 8 warps as 4(m) x 2(n); warp tile 32x64; mma m16n8k16.
// ============================================================
#define QPAD 264   // 256 + 8 bf16 pad (conflict-free fragment LDS)
#define SPAD 132   // sim row stride in floats
#define SIM_SMEM (128*QPAD*2 /*q*/ + 128*QPAD*2 /*keys*/ + 128*SPAD*4 /*sim*/ \
                  + 128*NCAND*4 /*tv*/ + 128*NCAND*4 /*ti*/)

__global__ __launch_bounds__(256, 1)
void sim_topk_kernel(const __nv_bfloat16* __restrict__ qb,
                     const __nv_bfloat16* __restrict__ kb,
                     int* __restrict__ cand) {
    extern __shared__ char smraw[];
    __nv_bfloat16* qs = (__nv_bfloat16*)smraw;            // [128][QPAD]
    __nv_bfloat16* ks = qs + 128 * QPAD;                  // [128][QPAD]
    float* sim = (float*)(ks + 128 * QPAD);               // [128][SPAD]
    float* tv  = sim + 128 * SPAD;                        // [128][16]
    int*   ti  = (int*)(tv + 128 * NCAND);                // [128][16]

    int tid = threadIdx.x, lane = tid & 31, warp = tid >> 5;
    int row0 = blockIdx.x * 128;

    // load q tile (bf16, already converted)
    for (int i = tid; i < 128 * 32; i += 256) {
        int r = i >> 5, u = i & 31;
        uint4 v = *(const uint4*)(qb + (size_t)(row0 + r) * 256 + u * 8);
        *(uint4*)(qs + r * QPAD + u * 8) = v;
    }
    for (int i = tid; i < 128 * NCAND; i += 256) { tv[i] = -1e30f; ti[i] = 0; }
    __syncthreads();

    int wm = warp >> 1, wn = warp & 1;
    int qr = lane >> 2, kc = (lane & 3) * 2;

    for (int ch = 0; ch < 32; ch++) {
        // stream keys chunk into smem
        for (int i = tid; i < 128 * 32; i += 256) {
            int r = i >> 5, u = i & 31;
            uint4 v = *(const uint4*)(kb + (size_t)(ch * 128 + r) * 256 + u * 8);
            *(uint4*)(ks + r * QPAD + u * 8) = v;
        }
        __syncthreads();

        float acc[2][8][4];
#pragma unroll
        for (int mt = 0; mt < 2; mt++)
#pragma unroll
            for (int nt = 0; nt < 8; nt++)
#pragma unroll
                for (int x = 0; x < 4; x++) acc[mt][nt][x] = 0.f;

#pragma unroll
        for (int ksp = 0; ksp < 16; ksp++) {
            int k0 = ksp * 16;
            unsigned A[2][4];
#pragma unroll
            for (int mt = 0; mt < 2; mt++) {
                const __nv_bfloat16* p0 = qs + (wm * 32 + mt * 16 + qr) * QPAD + k0 + kc;
                A[mt][0] = *(const unsigned*)(p0);
                A[mt][1] = *(const unsigned*)(p0 + 8 * QPAD);
                A[mt][2] = *(const unsigned*)(p0 + 8);
                A[mt][3] = *(const unsigned*)(p0 + 8 * QPAD + 8);
            }
#pragma unroll
            for (int nt = 0; nt < 8; nt++) {
                const __nv_bfloat16* pb = ks + (wn * 64 + nt * 8 + qr) * QPAD + k0 + kc;
                unsigned B0 = *(const unsigned*)(pb);
                unsigned B1 = *(const unsigned*)(pb + 8);
#pragma unroll
                for (int mt = 0; mt < 2; mt++) {
                    asm volatile(
                        "mma.sync.aligned.m16n8k16.row.col.f32.bf16.bf16.f32 "
                        "{%0,%1,%2,%3}, {%4,%5,%6,%7}, {%8,%9}, {%0,%1,%2,%3};\n"
                        : "+f"(acc[mt][nt][0]), "+f"(acc[mt][nt][1]),
                          "+f"(acc[mt][nt][2]), "+f"(acc[mt][nt][3])
                        : "r"(A[mt][0]), "r"(A[mt][1]), "r"(A[mt][2]), "r"(A[mt][3]),
                          "r"(B0), "r"(B1));
                }
            }
        }

        // stage sim tile to smem
#pragma unroll
        for (int mt = 0; mt < 2; mt++)
#pragma unroll
            for (int nt = 0; nt < 8; nt++) {
                int r = wm * 32 + mt * 16 + qr;
                int c = wn * 64 + nt * 8 + (lane & 3) * 2;
                *(float2*)&sim[r * SPAD + c] = make_float2(acc[mt][nt][0], acc[mt][nt][1]);
                *(float2*)&sim[(r + 8) * SPAD + c] = make_float2(acc[mt][nt][2], acc[mt][nt][3]);
            }
        __syncthreads();

        // streaming top-16 maintenance: warp owns rows warp*16..+15
        for (int rr = 0; rr < 16; rr++) {
            int r = warp * 16 + rr;
            float* tvr = tv + r * NCAND;
            int*   tir = ti + r * NCAND;
            float thresh = tvr[NCAND - 1];
#pragma unroll
            for (int j = 0; j < 4; j++) {
                float v = sim[r * SPAD + lane + j * 32];
                unsigned bal = __ballot_sync(FULL, v > thresh);
                while (bal) {
                    int src = __ffs(bal) - 1; bal &= bal - 1;
                    float vv = __shfl_sync(FULL, v, src);
                    if (vv > thresh) {
                        if (lane == 0) {
                            int p = NCAND - 1;
                            while (p > 0 && tvr[p - 1] < vv) {
                                tvr[p] = tvr[p - 1]; tir[p] = tir[p - 1]; p--;
                            }
                            tvr[p] = vv; tir[p] = ch * 128 + src + j * 32;
                        }
                        __syncwarp();
                        thresh = tvr[NCAND - 1];
                    }
                }
            }
        }
        __syncthreads();
    }

    for (int rr = 0; rr < 16; rr++) {
        int r = warp * 16 + rr;
        if (lane < NCAND) cand[(size_t)(row0 + r) * NCAND + lane] = ti[r * NCAND + lane];
    }
}

// ============================================================
// Exact rescore: fp32 dots for 16 candidates, exact top-8,
// softmax + weighted gather of memory_values. 1 warp per query.
// ============================================================
__global__ __launch_bounds__(256)
void rescore_kernel(const float* __restrict__ q, const float* __restrict__ keys,
                    const float* __restrict__ values, const int* __restrict__ cand,
                    float* __restrict__ ret) {
    int lane = threadIdx.x & 31, warp = threadIdx.x >> 5;
    int g = blockIdx.x * 8 + warp;

    float qv[8];
#pragma unroll
    for (int k = 0; k < 8; k++) qv[k] = q[(size_t)g * 256 + k * 32 + lane];

    int myc = cand[(size_t)g * NCAND + (lane & 15)];
    float s[NCAND]; int kid[NCAND];
#pragma unroll
    for (int c = 0; c < NCAND; c++) {
        int ki = __shfl_sync(FULL, myc, c);
        kid[c] = ki;
        const float* kr = keys + (size_t)ki * 256;
        float d = 0.f;
#pragma unroll
        for (int k = 0; k < 8; k++) d = fmaf(qv[k], kr[k * 32 + lane], d);
#pragma unroll
        for (int o = 16; o; o >>= 1) d += __shfl_xor_sync(FULL, d, o);
        s[c] = d;   // identical across lanes
    }

    bool sel[NCAND];
    float mx = -1e30f;
#pragma unroll
    for (int c = 0; c < NCAND; c++) {
        int rk = 0;
#pragma unroll
        for (int j = 0; j < NCAND; j++)
            rk += (s[j] > s[c]) || (s[j] == s[c] && j < c);
        sel[c] = (rk < TOPK);
        if (sel[c]) mx = fmaxf(mx, s[c]);
    }
    float den = 0.f, w[NCAND];
#pragma unroll
    for (int c = 0; c < NCAND; c++) {
        w[c] = sel[c] ? __expf(s[c] - mx) : 0.f;
        den += w[c];
    }
    float inv = 1.f / den;

    float accf[8];
#pragma unroll
    for (int k = 0; k < 8; k++) accf[k] = 0.f;
#pragma unroll
    for (int c = 0; c < NCAND; c++) {
        if (sel[c]) {
            const float* vr = values + (size_t)kid[c] * 256;
            float wc = w[c] * inv;
#pragma unroll
            for (int k = 0; k < 8; k++) accf[k] = fmaf(wc, vr[k * 32 + lane], accf[k]);
        }
    }
#pragma unroll
    for (int k = 0; k < 8; k++) ret[(size_t)g * 256 + k * 32 + lane] = accf[k];
}

// ============================================================
// launch
// ============================================================
extern "C" void kernel_launch(void* const* d_in, const int* in_sizes, int n_in,
                              void* d_out, int out_size) {
    const float* query = (const float*)d_in[0];
    const float* mkeys = (const float*)d_in[1];
    const float* mvals = (const float*)d_in[2];
    const float* Wq    = (const float*)d_in[3];
    const float* bq    = (const float*)d_in[4];
    const float* W1    = (const float*)d_in[5];
    const float* b1    = (const float*)d_in[6];
    const float* W2    = (const float*)d_in[7];
    const float* b2    = (const float*)d_in[8];
    float* out = (float*)d_out;
    (void)in_sizes; (void)n_in; (void)out_size;

    float* qf;           cudaGetSymbolAddress((void**)&qf, g_q);
    __nv_bfloat16* qbf;  cudaGetSymbolAddress((void**)&qbf, g_qb);
    __nv_bfloat16* kbf;  cudaGetSymbolAddress((void**)&kbf, g_kb);
    int* candp;          cudaGetSymbolAddress((void**)&candp, g_cand);
    float* retp;         cudaGetSymbolAddress((void**)&retp, g_ret);
    float* hp;           cudaGetSymbolAddress((void**)&hp, g_h);
    __nv_bfloat16 *wqh, *wql, *w1h, *w1l, *w2h, *w2l;
    cudaGetSymbolAddress((void**)&wqh, g_wqt_h);
    cudaGetSymbolAddress((void**)&wql, g_wqt_l);
    cudaGetSymbolAddress((void**)&w1h, g_w1t_h);
    cudaGetSymbolAddress((void**)&w1l, g_w1t_l);
    cudaGetSymbolAddress((void**)&w2h, g_w2t_h);
    cudaGetSymbolAddress((void**)&w2l, g_w2t_l);

    // keys -> bf16; weights -> transposed split-bf16
    conv_keys_kernel<<<(MMEM * FD / 4) / 256, 256>>>(mkeys, kbf);
    prep_wt_kernel<<<256, 256>>>(Wq, 256, wqh, wql);
    prep_wt_kernel<<<512, 256>>>(W1, 512, w1h, w1l);
    prep_wt_kernel<<<256, 256>>>(W2, 256, w2h, w2l);

    // q = query @ Wq + bq  (split-bf16 tensor cores; fp32 + bf16 outputs)
    cudaFuncSetAttribute(bgemm_kernel<256, 0, 0, 1>,
                         cudaFuncAttributeMaxDynamicSharedMemorySize, BG_SMEM);
    bgemm_kernel<256, 0, 0, 1><<<dim3(NROWS / 128, 2), 256, BG_SMEM>>>(
        query, nullptr, wqh, wql, bq, qf, qbf);

    // fused sim + top-16 candidates (bf16 tensor cores)
    cudaFuncSetAttribute(sim_topk_kernel,
                         cudaFuncAttributeMaxDynamicSharedMemorySize, SIM_SMEM);
    sim_topk_kernel<<<NROWS / 128, 256, SIM_SMEM>>>(qbf, kbf, candp);

    // exact rescore + softmax + gather
    rescore_kernel<<<NROWS / 8, 256>>>(qf, mkeys, mvals, candp, retp);

    // MLP: h = relu(concat(query, retrieved) @ W1 + b1); out = h @ W2 + b2
    cudaFuncSetAttribute(bgemm_kernel<512, 1, 1, 0>,
                         cudaFuncAttributeMaxDynamicSharedMemorySize, BG_SMEM);
    bgemm_kernel<512, 1, 1, 0><<<dim3(NROWS / 128, 2), 256, BG_SMEM>>>(
        query, retp, w1h, w1l, b1, hp, nullptr);

    cudaFuncSetAttribute(bgemm_kernel<256, 0, 0, 0>,
                         cudaFuncAttributeMaxDynamicSharedMemorySize, BG_SMEM);
    bgemm_kernel<256, 0, 0, 0><<<dim3(NROWS / 128, 2), 256, BG_SMEM>>>(
        hp, nullptr, w2h, w2l, b2, out, nullptr);
}

// round 7
// speedup vs baseline: 1.2390x; 1.0622x over previous
#include <cuda_runtime.h>
#include <cuda_bf16.h>
#include <cstdint>

#define FULL 0xffffffffu
#define NROWS 65536          // B*N
#define FD 256               // feature dim
#define MMEM 4096            // memory size
#define NCAND 16             // candidates kept (top-16), exact rescore picks top-8
#define TOPK 8

// -------- scratch (static __device__ — no allocations) --------
__device__ __align__(256) float         g_q[(size_t)NROWS * FD];   // fp32 q (rescore)
__device__ __align__(256) __nv_bfloat16 g_qb[(size_t)NROWS * FD];  // hi(q) for sim
__device__ __align__(256) __nv_bfloat16 g_kb[(size_t)MMEM * FD];   // bf16 keys
__device__ __align__(256) int           g_cand[(size_t)NROWS * NCAND];
__device__ __align__(256) __nv_bfloat16 g_qry_h[(size_t)NROWS * FD];
__device__ __align__(256) __nv_bfloat16 g_qry_l[(size_t)NROWS * FD];
__device__ __align__(256) __nv_bfloat16 g_ret_h[(size_t)NROWS * FD];
__device__ __align__(256) __nv_bfloat16 g_ret_l[(size_t)NROWS * FD];
__device__ __align__(256) __nv_bfloat16 g_h_h[(size_t)NROWS * FD];
__device__ __align__(256) __nv_bfloat16 g_h_l[(size_t)NROWS * FD];
// split-bf16 transposed weights: [N=256][K] k-major, hi + lo
__device__ __align__(256) __nv_bfloat16 g_wqt_h[256 * 256], g_wqt_l[256 * 256];
__device__ __align__(256) __nv_bfloat16 g_w1t_h[256 * 512], g_w1t_l[256 * 512];
__device__ __align__(256) __nv_bfloat16 g_w2t_h[256 * 256], g_w2t_l[256 * 256];

// order-preserving float->uint map (monotone; all finite floats map > 0)
__device__ __forceinline__ unsigned ford(float f) {
    unsigned u = __float_as_uint(f);
    return (u & 0x80000000u) ? ~u : (u | 0x80000000u);
}

// ============================================================
// keys -> bf16
// ============================================================
__global__ void conv_keys_kernel(const float* __restrict__ keys,
                                 __nv_bfloat16* __restrict__ out) {
    int i = blockIdx.x * blockDim.x + threadIdx.x;   // over MMEM*FD/4
    float4 v = ((const float4*)keys)[i];
    union { __nv_bfloat16 h[4]; uint2 u; } p;
    p.h[0] = __float2bfloat16_rn(v.x);
    p.h[1] = __float2bfloat16_rn(v.y);
    p.h[2] = __float2bfloat16_rn(v.z);
    p.h[3] = __float2bfloat16_rn(v.w);
    ((uint2*)out)[i] = p.u;
}

// ============================================================
// weight prep: W[K][256] -> transposed split-bf16 [256 n][K k]
// ============================================================
__global__ void prep_wt_kernel(const float* __restrict__ W, int K,
                               __nv_bfloat16* __restrict__ th,
                               __nv_bfloat16* __restrict__ tl) {
    int idx = blockIdx.x * 256 + threadIdx.x;   // over 256*K
    int n = idx / K, k = idx - n * K;
    float v = W[(size_t)k * 256 + n];
    __nv_bfloat16 h = __float2bfloat16_rn(v);
    float r = v - __bfloat162float(h);
    th[(size_t)n * K + k] = h;
    tl[(size_t)n * K + k] = __float2bfloat16_rn(r);
}

// ============================================================
// fp32 -> split bf16 hi/lo (row-layout preserved)
// ============================================================
__global__ void split_f32_kernel(const float* __restrict__ x,
                                 __nv_bfloat16* __restrict__ xh,
                                 __nv_bfloat16* __restrict__ xl) {
    size_t i = (size_t)blockIdx.x * blockDim.x + threadIdx.x;  // over count/4
    float4 v = ((const float4*)x)[i];
    union { __nv_bfloat16 h[4]; uint2 u; } ph, pl;
    float f[4] = {v.x, v.y, v.z, v.w};
#pragma unroll
    for (int j = 0; j < 4; j++) {
        ph.h[j] = __float2bfloat16_rn(f[j]);
        pl.h[j] = __float2bfloat16_rn(f[j] - __bfloat162float(ph.h[j]));
    }
    ((uint2*)xh)[i] = ph.u;
    ((uint2*)xl)[i] = pl.u;
}

// ============================================================
// split-bf16 tensor-core GEMM v2: preconverted hi/lo A in gmem,
// cp.async 2-stage pipeline. BM=128, BN=128, BK=64.
// MODE 0: C fp32.  MODE 1: C fp32 + Ch (bf16 hi).  MODE 2: Ch+Cl (hi/lo).
// CONCAT: A = [A0 | A1] along K (each row-stride 256).
// ============================================================
#define APAD 72                              // staged row stride (bf16)
#define BG_STAGE (4 * 128 * APAD * 2)        // Ah, Al, Bh, Bl per stage
#define BG_SMEM (2 * BG_STAGE)

__device__ __forceinline__ void cp16(unsigned dst, const void* src) {
    asm volatile("cp.async.cg.shared.global [%0], [%1], 16;\n"
                 :: "r"(dst), "l"(src) : "memory");
}

template <int K, int CONCAT, int RELU, int MODE>
__global__ __launch_bounds__(256)
void bgemm2_kernel(const __nv_bfloat16* __restrict__ A0h,
                   const __nv_bfloat16* __restrict__ A0l,
                   const __nv_bfloat16* __restrict__ A1h,
                   const __nv_bfloat16* __restrict__ A1l,
                   const __nv_bfloat16* __restrict__ Bth,
                   const __nv_bfloat16* __restrict__ Btl,
                   const float* __restrict__ bias,
                   float* __restrict__ C,
                   __nv_bfloat16* __restrict__ Ch,
                   __nv_bfloat16* __restrict__ Cl) {
    extern __shared__ char smraw[];
    unsigned sbase = (unsigned)__cvta_generic_to_shared(smraw);
    int tid = threadIdx.x, lane = tid & 31, warp = tid >> 5;
    int row0 = blockIdx.x * 128, col0 = blockIdx.y * 128;
    const int NITER = K / 64;

    auto prefetch = [&](int it, int buf) {
        int kb = it * 64;
        const __nv_bfloat16 *Ah, *Al;
        if (CONCAT && kb >= 256) { Ah = A1h + (kb - 256); Al = A1l + (kb - 256); }
        else                     { Ah = A0h + kb;         Al = A0l + kb;         }
        const int astr = CONCAT ? 256 : K;
        unsigned s = sbase + buf * BG_STAGE;
#pragma unroll
        for (int t = 0; t < 4; t++) {
            int g = tid + t * 256;             // 1024 uint4 per operand
            int r = g >> 3, q = (g & 7) * 8;
            unsigned off = (unsigned)(r * APAD + q) * 2;
            cp16(s + off,                      Ah + (size_t)(row0 + r) * astr + q);
            cp16(s + 128 * APAD * 2 + off,     Al + (size_t)(row0 + r) * astr + q);
            cp16(s + 2 * 128 * APAD * 2 + off, Bth + (size_t)(col0 + r) * K + kb + q);
            cp16(s + 3 * 128 * APAD * 2 + off, Btl + (size_t)(col0 + r) * K + kb + q);
        }
        asm volatile("cp.async.commit_group;\n" ::: "memory");
    };

    int wm = warp >> 1, wn = warp & 1;
    int qr = lane >> 2, kc = (lane & 3) * 2;

    float acc[2][8][4];
#pragma unroll
    for (int mt = 0; mt < 2; mt++)
#pragma unroll
        for (int nt = 0; nt < 8; nt++)
#pragma unroll
            for (int x = 0; x < 4; x++) acc[mt][nt][x] = 0.f;

    prefetch(0, 0);

    for (int it = 0; it < NITER; it++) {
        if (it + 1 < NITER) {
            prefetch(it + 1, (it + 1) & 1);
            asm volatile("cp.async.wait_group 1;\n" ::: "memory");
        } else {
            asm volatile("cp.async.wait_group 0;\n" ::: "memory");
        }
        __syncthreads();
        __nv_bfloat16* Ash = (__nv_bfloat16*)(smraw + (it & 1) * BG_STAGE);
        __nv_bfloat16* Asl = Ash + 128 * APAD;
        __nv_bfloat16* Bsh = Asl + 128 * APAD;
        __nv_bfloat16* Bsl = Bsh + 128 * APAD;

#pragma unroll
        for (int ksp = 0; ksp < 4; ksp++) {
            int k0 = ksp * 16;
            unsigned Ahf[2][4], Alf[2][4];
#pragma unroll
            for (int mt = 0; mt < 2; mt++) {
                const __nv_bfloat16* ph = Ash + (wm * 32 + mt * 16 + qr) * APAD + k0 + kc;
                const __nv_bfloat16* pl = Asl + (wm * 32 + mt * 16 + qr) * APAD + k0 + kc;
                Ahf[mt][0] = *(const unsigned*)(ph);
                Ahf[mt][1] = *(const unsigned*)(ph + 8 * APAD);
                Ahf[mt][2] = *(const unsigned*)(ph + 8);
                Ahf[mt][3] = *(const unsigned*)(ph + 8 * APAD + 8);
                Alf[mt][0] = *(const unsigned*)(pl);
                Alf[mt][1] = *(const unsigned*)(pl + 8 * APAD);
                Alf[mt][2] = *(const unsigned*)(pl + 8);
                Alf[mt][3] = *(const unsigned*)(pl + 8 * APAD + 8);
            }
#pragma unroll
            for (int nt = 0; nt < 8; nt++) {
                const __nv_bfloat16* pbh = Bsh + (wn * 64 + nt * 8 + qr) * APAD + k0 + kc;
                const __nv_bfloat16* pbl = Bsl + (wn * 64 + nt * 8 + qr) * APAD + k0 + kc;
                unsigned Bh0 = *(const unsigned*)(pbh);
                unsigned Bh1 = *(const unsigned*)(pbh + 8);
                unsigned Bl0 = *(const unsigned*)(pbl);
                unsigned Bl1 = *(const unsigned*)(pbl + 8);
#pragma unroll
                for (int mt = 0; mt < 2; mt++) {
#define MMA_BF16(Areg, B0, B1)                                              \
    asm volatile(                                                           \
        "mma.sync.aligned.m16n8k16.row.col.f32.bf16.bf16.f32 "              \
        "{%0,%1,%2,%3}, {%4,%5,%6,%7}, {%8,%9}, {%0,%1,%2,%3};\n"           \
        : "+f"(acc[mt][nt][0]), "+f"(acc[mt][nt][1]),                       \
          "+f"(acc[mt][nt][2]), "+f"(acc[mt][nt][3])                       \
        : "r"(Areg[mt][0]), "r"(Areg[mt][1]), "r"(Areg[mt][2]),             \
          "r"(Areg[mt][3]), "r"(B0), "r"(B1))
                    MMA_BF16(Ahf, Bh0, Bh1);   // hi*hi
                    MMA_BF16(Ahf, Bl0, Bl1);   // hi*lo
                    MMA_BF16(Alf, Bh0, Bh1);   // lo*hi
#undef MMA_BF16
                }
            }
        }
        __syncthreads();
    }

    // epilogue
#pragma unroll
    for (int mt = 0; mt < 2; mt++) {
        int rA = row0 + wm * 32 + mt * 16 + qr;
#pragma unroll
        for (int nt = 0; nt < 8; nt++) {
            int c = col0 + wn * 64 + nt * 8 + (lane & 3) * 2;
            float b0 = bias[c], b1 = bias[c + 1];
            float v0 = acc[mt][nt][0] + b0, v1 = acc[mt][nt][1] + b1;
            float v2 = acc[mt][nt][2] + b0, v3 = acc[mt][nt][3] + b1;
            if (RELU) {
                v0 = fmaxf(v0, 0.f); v1 = fmaxf(v1, 0.f);
                v2 = fmaxf(v2, 0.f); v3 = fmaxf(v3, 0.f);
            }
            if (MODE == 0 || MODE == 1) {
                *(float2*)(C + (size_t)rA * 256 + c)       = make_float2(v0, v1);
                *(float2*)(C + (size_t)(rA + 8) * 256 + c) = make_float2(v2, v3);
            }
            if (MODE == 1) {
                union { __nv_bfloat16 h[2]; unsigned u; } p;
                p.h[0] = __float2bfloat16_rn(v0); p.h[1] = __float2bfloat16_rn(v1);
                *(unsigned*)(Ch + (size_t)rA * 256 + c) = p.u;
                p.h[0] = __float2bfloat16_rn(v2); p.h[1] = __float2bfloat16_rn(v3);
                *(unsigned*)(Ch + (size_t)(rA + 8) * 256 + c) = p.u;
            }
            if (MODE == 2) {
                union { __nv_bfloat16 h[2]; unsigned u; } p, q;
                p.h[0] = __float2bfloat16_rn(v0);
                p.h[1] = __float2bfloat16_rn(v1);
                q.h[0] = __float2bfloat16_rn(v0 - __bfloat162float(p.h[0]));
                q.h[1] = __float2bfloat16_rn(v1 - __bfloat162float(p.h[1]));
                *(unsigned*)(Ch + (size_t)rA * 256 + c) = p.u;
                *(unsigned*)(Cl + (size_t)rA * 256 + c) = q.u;
                p.h[0] = __float2bfloat16_rn(v2);
                p.h[1] = __float2bfloat16_rn(v3);
                q.h[0] = __float2bfloat16_rn(v2 - __bfloat162float(p.h[0]));
                q.h[1] = __float2bfloat16_rn(v3 - __bfloat162float(p.h[1]));
                *(unsigned*)(Ch + (size_t)(rA + 8) * 256 + c) = p.u;
                *(unsigned*)(Cl + (size_t)(rA + 8) * 256 + c) = q.u;
            }
        }
    }
}

// ============================================================
// Fused sim GEMM (bf16 mma.sync) + parallel streaming top-16.
// 128-query tile per CTA, 32 chunks of 128 keys, K=256.
// Topk: unsorted 16-slot buffer per row; min via redux.sync.min.u32
// on order-mapped floats; 2 rows per warp concurrently (16-lane halves).
// ============================================================
#define QPAD 264   // 256 + 8 bf16 pad (conflict-free fragment LDS)
#define SPAD 144   // sim row stride in floats (144 % 32 == 16 -> halves hit
                   // disjoint bank sets for adjacent rows)
#define SIM_SMEM (128*QPAD*2 /*q*/ + 128*QPAD*2 /*keys*/ + 128*SPAD*4 /*sim*/ \
                  + 128*NCAND*4 /*tvu*/ + 128*NCAND*4 /*ti*/)

__global__ __launch_bounds__(256, 1)
void sim_topk_kernel(const __nv_bfloat16* __restrict__ qb,
                     const __nv_bfloat16* __restrict__ kb,
                     int* __restrict__ cand) {
    extern __shared__ char smraw[];
    __nv_bfloat16* qs = (__nv_bfloat16*)smraw;            // [128][QPAD]
    __nv_bfloat16* ks = qs + 128 * QPAD;                  // [128][QPAD]
    float*    sim = (float*)(ks + 128 * QPAD);            // [128][SPAD]
    unsigned* tvu = (unsigned*)(sim + 128 * SPAD);        // [128][16] slot vals
    int*      ti  = (int*)(tvu + 128 * NCAND);            // [128][16] slot idxs

    int tid = threadIdx.x, lane = tid & 31, warp = tid >> 5;
    int row0 = blockIdx.x * 128;

    // load q tile (bf16 hi, already converted)
    for (int i = tid; i < 128 * 32; i += 256) {
        int r = i >> 5, u = i & 31;
        uint4 v = *(const uint4*)(qb + (size_t)(row0 + r) * 256 + u * 8);
        *(uint4*)(qs + r * QPAD + u * 8) = v;
    }
    __syncthreads();

    int wm = warp >> 1, wn = warp & 1;
    int qr = lane >> 2, kc = (lane & 3) * 2;
    int half = lane >> 4, sl = lane & 15;
    unsigned hm = half ? 0xFFFF0000u : 0x0000FFFFu;

    for (int ch = 0; ch < 32; ch++) {
        // stream keys chunk into smem
        for (int i = tid; i < 128 * 32; i += 256) {
            int r = i >> 5, u = i & 31;
            uint4 v = *(const uint4*)(kb + (size_t)(ch * 128 + r) * 256 + u * 8);
            *(uint4*)(ks + r * QPAD + u * 8) = v;
        }
        __syncthreads();

        float acc[2][8][4];
#pragma unroll
        for (int mt = 0; mt < 2; mt++)
#pragma unroll
            for (int nt = 0; nt < 8; nt++)
#pragma unroll
                for (int x = 0; x < 4; x++) acc[mt][nt][x] = 0.f;

#pragma unroll
        for (int ksp = 0; ksp < 16; ksp++) {
            int k0 = ksp * 16;
            unsigned A[2][4];
#pragma unroll
            for (int mt = 0; mt < 2; mt++) {
                const __nv_bfloat16* p0 = qs + (wm * 32 + mt * 16 + qr) * QPAD + k0 + kc;
                A[mt][0] = *(const unsigned*)(p0);
                A[mt][1] = *(const unsigned*)(p0 + 8 * QPAD);
                A[mt][2] = *(const unsigned*)(p0 + 8);
                A[mt][3] = *(const unsigned*)(p0 + 8 * QPAD + 8);
            }
#pragma unroll
            for (int nt = 0; nt < 8; nt++) {
                const __nv_bfloat16* pb = ks + (wn * 64 + nt * 8 + qr) * QPAD + k0 + kc;
                unsigned B0 = *(const unsigned*)(pb);
                unsigned B1 = *(const unsigned*)(pb + 8);
#pragma unroll
                for (int mt = 0; mt < 2; mt++) {
                    asm volatile(
                        "mma.sync.aligned.m16n8k16.row.col.f32.bf16.bf16.f32 "
                        "{%0,%1,%2,%3}, {%4,%5,%6,%7}, {%8,%9}, {%0,%1,%2,%3};\n"
                        : "+f"(acc[mt][nt][0]), "+f"(acc[mt][nt][1]),
                          "+f"(acc[mt][nt][2]), "+f"(acc[mt][nt][3])
                        : "r"(A[mt][0]), "r"(A[mt][1]), "r"(A[mt][2]), "r"(A[mt][3]),
                          "r"(B0), "r"(B1));
                }
            }
        }

        // stage sim tile to smem
#pragma unroll
        for (int mt = 0; mt < 2; mt++)
#pragma unroll
            for (int nt = 0; nt < 8; nt++) {
                int r = wm * 32 + mt * 16 + qr;
                int c = wn * 64 + nt * 8 + (lane & 3) * 2;
                *(float2*)&sim[r * SPAD + c] = make_float2(acc[mt][nt][0], acc[mt][nt][1]);
                *(float2*)&sim[(r + 8) * SPAD + c] = make_float2(acc[mt][nt][2], acc[mt][nt][3]);
            }
        __syncthreads();

        // ---- parallel top-16: warp handles rows warp*16..+15 as 8 pairs ----
#pragma unroll 1
        for (int p = 0; p < 8; p++) {
            int r = warp * 16 + 2 * p + half;
            unsigned su; int sidx;
            if (ch == 0) { su = 0u; sidx = 0; }
            else { su = tvu[r * 16 + sl]; sidx = ti[r * 16 + sl]; }
            unsigned mn = __reduce_min_sync(hm, su);
            const float* simr = sim + r * SPAD;
#pragma unroll 1
            for (int j = 0; j < 8; j++) {
                unsigned up = ford(simr[j * 16 + sl]);
                unsigned bal = __ballot_sync(hm, up > mn);
                unsigned hbal = (half ? (bal >> 16) : bal) & 0xFFFFu;
                while (hbal) {
                    int s = __ffs(hbal) - 1; hbal &= hbal - 1;
                    unsigned cu = __shfl_sync(hm, up, (half << 4) + s);
                    if (cu > mn) {
                        unsigned mb = __ballot_sync(hm, su == mn);
                        int ms = __ffs(half ? (mb >> 16) : mb) - 1;
                        if (sl == ms) { su = cu; sidx = ch * 128 + j * 16 + s; }
                        mn = __reduce_min_sync(hm, su);
                    }
                }
            }
            tvu[r * 16 + sl] = su;
            ti[r * 16 + sl] = sidx;
        }
        __syncthreads();
    }

    for (int rr = 0; rr < 16; rr++) {
        int r = warp * 16 + rr;
        if (lane < NCAND) cand[(size_t)(row0 + r) * NCAND + lane] = ti[r * 16 + lane];
    }
}

// ============================================================
// Exact rescore: fp32 dots for 16 candidates, exact top-8,
// softmax + weighted gather of memory_values. 1 warp per query.
// Emits retrieved as split-bf16 hi/lo (for the MLP1 tensor-core GEMM).
// ============================================================
__global__ __launch_bounds__(256)
void rescore_kernel(const float* __restrict__ q, const float* __restrict__ keys,
                    const float* __restrict__ values, const int* __restrict__ cand,
                    __nv_bfloat16* __restrict__ reth, __nv_bfloat16* __restrict__ retl) {
    int lane = threadIdx.x & 31, warp = threadIdx.x >> 5;
    int g = blockIdx.x * 8 + warp;

    float qv[8];
#pragma unroll
    for (int k = 0; k < 8; k++) qv[k] = q[(size_t)g * 256 + k * 32 + lane];

    int myc = cand[(size_t)g * NCAND + (lane & 15)];
    float s[NCAND]; int kid[NCAND];
#pragma unroll
    for (int c = 0; c < NCAND; c++) {
        int ki = __shfl_sync(FULL, myc, c);
        kid[c] = ki;
        const float* kr = keys + (size_t)ki * 256;
        float d = 0.f;
#pragma unroll
        for (int k = 0; k < 8; k++) d = fmaf(qv[k], kr[k * 32 + lane], d);
#pragma unroll
        for (int o = 16; o; o >>= 1) d += __shfl_xor_sync(FULL, d, o);
        s[c] = d;   // identical across lanes
    }

    bool sel[NCAND];
    float mx = -1e30f;
#pragma unroll
    for (int c = 0; c < NCAND; c++) {
        int rk = 0;
#pragma unroll
        for (int j = 0; j < NCAND; j++)
            rk += (s[j] > s[c]) || (s[j] == s[c] && j < c);
        sel[c] = (rk < TOPK);
        if (sel[c]) mx = fmaxf(mx, s[c]);
    }
    float den = 0.f, w[NCAND];
#pragma unroll
    for (int c = 0; c < NCAND; c++) {
        w[c] = sel[c] ? __expf(s[c] - mx) : 0.f;
        den += w[c];
    }
    float inv = 1.f / den;

    float accf[8];
#pragma unroll
    for (int k = 0; k < 8; k++) accf[k] = 0.f;
#pragma unroll
    for (int c = 0; c < NCAND; c++) {
        if (sel[c]) {
            const float* vr = values + (size_t)kid[c] * 256;
            float wc = w[c] * inv;
#pragma unroll
            for (int k = 0; k < 8; k++) accf[k] = fmaf(wc, vr[k * 32 + lane], accf[k]);
        }
    }
#pragma unroll
    for (int k = 0; k < 8; k++) {
        float v = accf[k];
        __nv_bfloat16 hi = __float2bfloat16_rn(v);
        reth[(size_t)g * 256 + k * 32 + lane] = hi;
        retl[(size_t)g * 256 + k * 32 + lane] =
            __float2bfloat16_rn(v - __bfloat162float(hi));
    }
}

// ============================================================
// launch
// ============================================================
extern "C" void kernel_launch(void* const* d_in, const int* in_sizes, int n_in,
                              void* d_out, int out_size) {
    const float* query = (const float*)d_in[0];
    const float* mkeys = (const float*)d_in[1];
    const float* mvals = (const float*)d_in[2];
    const float* Wq    = (const float*)d_in[3];
    const float* bq    = (const float*)d_in[4];
    const float* W1    = (const float*)d_in[5];
    const float* b1    = (const float*)d_in[6];
    const float* W2    = (const float*)d_in[7];
    const float* b2    = (const float*)d_in[8];
    float* out = (float*)d_out;
    (void)in_sizes; (void)n_in; (void)out_size;

    float* qf;           cudaGetSymbolAddress((void**)&qf, g_q);
    __nv_bfloat16* qbf;  cudaGetSymbolAddress((void**)&qbf, g_qb);
    __nv_bfloat16* kbf;  cudaGetSymbolAddress((void**)&kbf, g_kb);
    int* candp;          cudaGetSymbolAddress((void**)&candp, g_cand);
    __nv_bfloat16 *qryh, *qryl, *reth, *retl, *hh, *hl;
    cudaGetSymbolAddress((void**)&qryh, g_qry_h);
    cudaGetSymbolAddress((void**)&qryl, g_qry_l);
    cudaGetSymbolAddress((void**)&reth, g_ret_h);
    cudaGetSymbolAddress((void**)&retl, g_ret_l);
    cudaGetSymbolAddress((void**)&hh,   g_h_h);
    cudaGetSymbolAddress((void**)&hl,   g_h_l);
    __nv_bfloat16 *wqh, *wql, *w1h, *w1l, *w2h, *w2l;
    cudaGetSymbolAddress((void**)&wqh, g_wqt_h);
    cudaGetSymbolAddress((void**)&wql, g_wqt_l);
    cudaGetSymbolAddress((void**)&w1h, g_w1t_h);
    cudaGetSymbolAddress((void**)&w1l, g_w1t_l);
    cudaGetSymbolAddress((void**)&w2h, g_w2t_h);
    cudaGetSymbolAddress((void**)&w2l, g_w2t_l);

    // 0: keys -> bf16;  1-3: weights -> transposed split-bf16;  4: query split
    conv_keys_kernel<<<(MMEM * FD / 4) / 256, 256>>>(mkeys, kbf);
    prep_wt_kernel<<<256, 256>>>(Wq, 256, wqh, wql);
    prep_wt_kernel<<<512, 256>>>(W1, 512, w1h, w1l);
    prep_wt_kernel<<<256, 256>>>(W2, 256, w2h, w2l);
    split_f32_kernel<<<(NROWS * FD / 4) / 256, 256>>>(query, qryh, qryl);

    // 5: q = query @ Wq + bq   (fp32 out + bf16 hi out)
    cudaFuncSetAttribute(bgemm2_kernel<256, 0, 0, 1>,
                         cudaFuncAttributeMaxDynamicSharedMemorySize, BG_SMEM);
    bgemm2_kernel<256, 0, 0, 1><<<dim3(NROWS / 128, 2), 256, BG_SMEM>>>(
        qryh, qryl, nullptr, nullptr, wqh, wql, bq, qf, qbf, nullptr);

    // 6: fused sim + top-16 candidates
    cudaFuncSetAttribute(sim_topk_kernel,
                         cudaFuncAttributeMaxDynamicSharedMemorySize, SIM_SMEM);
    sim_topk_kernel<<<NROWS / 128, 256, SIM_SMEM>>>(qbf, kbf, candp);

    // 7: exact rescore + softmax + gather (-> split-bf16 retrieved)
    rescore_kernel<<<NROWS / 8, 256>>>(qf, mkeys, mvals, candp, reth, retl);

    // 8: h = relu(concat(query, retrieved) @ W1 + b1)  (-> split-bf16 h)
    cudaFuncSetAttribute(bgemm2_kernel<512, 1, 1, 2>,
                         cudaFuncAttributeMaxDynamicSharedMemorySize, BG_SMEM);
    bgemm2_kernel<512, 1, 1, 2><<<dim3(NROWS / 128, 2), 256, BG_SMEM>>>(
        qryh, qryl, reth, retl, w1h, w1l, b1, nullptr, hh, hl);

    // 9: out = h @ W2 + b2  (fp32)
    cudaFuncSetAttribute(bgemm2_kernel<256, 0, 0, 0>,
                         cudaFuncAttributeMaxDynamicSharedMemorySize, BG_SMEM);
    bgemm2_kernel<256, 0, 0, 0><<<dim3(NROWS / 128, 2), 256, BG_SMEM>>>(
        hh, hl, nullptr, nullptr, w2h, w2l, b2, out, nullptr, nullptr);
}